// round 2
// baseline (speedup 1.0000x reference)
#include <cuda_runtime.h>
#include <cstdio>

#define NT   343      // tokens per window (7*7*7)
#define CDIM 96       // embedding dim
#define HD   32       // head dim
#define NH   3        // heads
#define NW   64       // windows per batch group
#define BTOT 512      // total "b" (batch * windows)

// ---------------- scratch (static device globals: allocation-free) ----------------
__device__ float g_bm[(size_t)NW * NH * NT * NT];      // bias+mask, transposed [w,h][m][n]  (~90 MB)
__device__ float g_attn[(size_t)BTOT * NT * CDIM];     // attention output before proj       (~67 MB)

// swizzled K/V smem offset: row m, float4-quad dq  (conflict-free writes, broadcast reads)
__device__ __forceinline__ int kvoff(int m, int dq) {
    return m * HD + ((dq ^ (m & 7)) << 2);
}

// ============================ K0: bias+mask precombine (transposed) ============================
// g_bm[(w*3+h)][m][n] = mask[w][n][m] + rpb_table[rel_index[n][m]][h]
__global__ void bm_kernel(const float* __restrict__ mask,
                          const float* __restrict__ rpb,
                          const int*   __restrict__ ridx) {
    __shared__ float mt[32][33];
    __shared__ int   rt[32][33];
    const int w  = blockIdx.y;
    const int t  = blockIdx.x;            // 0..120
    const int tm = (t % 11) * 32;         // m tile base
    const int tn = (t / 11) * 32;         // n tile base
    const int tid = threadIdx.x;

    for (int i = tid; i < 1024; i += 256) {
        int r = i / 32;        // local n
        int c = i % 32;        // local m
        int n = tn + r, m = tm + c;
        if (n < NT && m < NT) {
            mt[r][c] = mask[((size_t)w * NT + n) * NT + m];
            rt[r][c] = ridx[n * NT + m];
        }
    }
    __syncthreads();
    for (int i = tid; i < 1024; i += 256) {
        int r = i / 32;        // local m
        int c = i % 32;        // local n
        int n = tn + c, m = tm + r;
        if (n < NT && m < NT) {
            float mv = mt[c][r];
            int   ri = rt[c][r];
#pragma unroll
            for (int hh = 0; hh < NH; hh++) {
                g_bm[(((size_t)w * NH + hh) * NT + m) * NT + n] = mv + __ldg(rpb + ri * NH + hh);
            }
        }
    }
}

// ============================ K1: fused QKV + attention per (b,h) ============================
// smem layout (floats): xs[96][343] | ks[343][32] | vs[343][32] | ws[96][32]
#define SMEM_K1_FLOATS (CDIM*NT + NT*HD + NT*HD + CDIM*HD)

__global__ __launch_bounds__(352, 1)
void attn_kernel(const float* __restrict__ x,
                 const float* __restrict__ qkv_w,
                 const float* __restrict__ qkv_b) {
    extern __shared__ float sm[];
    float* xs = sm;                        // [c][n]  transposed x
    float* ks = xs + CDIM * NT;            // [m][d]  swizzled
    float* vs = ks + NT * HD;              // [m][d]  swizzled
    float* ws = vs + NT * HD;              // [c][d]  current weight matrix

    const int b   = blockIdx.x;
    const int h   = blockIdx.y;
    const int tid = threadIdx.x;
    const int n   = tid;                   // query/key row owned by this thread
    const float scale = 0.17677669529663689f;   // 32^-0.5

    // ---- load x[b] transposed into xs (coalesced float4 reads) ----
    {
        const float4* xb = (const float4*)(x + (size_t)b * NT * CDIM);
        for (int idx = tid; idx < NT * CDIM / 4; idx += blockDim.x) {
            float4 v = __ldg(xb + idx);
            int e = idx * 4;
            int row = e / CDIM, c = e % CDIM;
            xs[(c + 0) * NT + row] = v.x;
            xs[(c + 1) * NT + row] = v.y;
            xs[(c + 2) * NT + row] = v.z;
            xs[(c + 3) * NT + row] = v.w;
        }
    }
    __syncthreads();

    float q[HD];

    // ---- phase A: three weight passes (K, V, then Q last so q stays in regs) ----
#pragma unroll 1
    for (int pass = 0; pass < 3; pass++) {
        const int sel  = (pass == 0) ? 1 : (pass == 1) ? 2 : 0;   // k, v, q
        const int base = sel * CDIM + h * HD;

        // load W[sel,h] into ws[c][d]  (coalesced global reads)
        for (int i = tid; i < CDIM * HD; i += blockDim.x) {
            ws[(i % CDIM) * HD + (i / CDIM)] = __ldg(qkv_w + (size_t)base * CDIM + i);
        }
        __syncthreads();

        if (n < NT) {
            float acc[HD];
#pragma unroll
            for (int d = 0; d < HD; d++) acc[d] = __ldg(qkv_b + base + d);
#pragma unroll 4
            for (int c = 0; c < CDIM; c++) {
                float xv = xs[c * NT + n];
#pragma unroll
                for (int dq = 0; dq < HD / 4; dq++) {
                    float4 w4 = *(const float4*)(ws + c * HD + dq * 4);
                    acc[4 * dq + 0] += xv * w4.x;
                    acc[4 * dq + 1] += xv * w4.y;
                    acc[4 * dq + 2] += xv * w4.z;
                    acc[4 * dq + 3] += xv * w4.w;
                }
            }
            if (sel == 1) {
#pragma unroll
                for (int dq = 0; dq < HD / 4; dq++)
                    *(float4*)(ks + kvoff(n, dq)) =
                        make_float4(acc[4*dq], acc[4*dq+1], acc[4*dq+2], acc[4*dq+3]);
            } else if (sel == 2) {
#pragma unroll
                for (int dq = 0; dq < HD / 4; dq++)
                    *(float4*)(vs + kvoff(n, dq)) =
                        make_float4(acc[4*dq], acc[4*dq+1], acc[4*dq+2], acc[4*dq+3]);
            } else {
#pragma unroll
                for (int d = 0; d < HD; d++) q[d] = acc[d] * scale;
            }
        }
        __syncthreads();
    }

    // ---- phase B: online-softmax attention, 8-key chunks ----
    if (n < NT) {
        const float* bmrow = g_bm + (((size_t)(b % NW) * NH + h) * NT) * NT;  // [m][n]
        float o[HD];
#pragma unroll
        for (int d = 0; d < HD; d++) o[d] = 0.f;
        float mrun = -1e30f, lrun = 0.f;

        for (int mb = 0; mb < NT; mb += 8) {
            float s[8];
#pragma unroll
            for (int j = 0; j < 8; j++) {
                int m = mb + j;
                s[j] = (m < NT) ? __ldg(bmrow + (size_t)m * NT + n) : -1e30f;  // coalesced over n
            }
#pragma unroll
            for (int j = 0; j < 8; j++) {
                int m = mb + j;
                if (m < NT) {
                    float sj = s[j];
#pragma unroll
                    for (int dq = 0; dq < HD / 4; dq++) {
                        float4 k4 = *(const float4*)(ks + kvoff(m, dq));   // broadcast LDS128
                        sj += q[4*dq+0] * k4.x;
                        sj += q[4*dq+1] * k4.y;
                        sj += q[4*dq+2] * k4.z;
                        sj += q[4*dq+3] * k4.w;
                    }
                    s[j] = sj;
                }
            }
            float cm = s[0];
#pragma unroll
            for (int j = 1; j < 8; j++) cm = fmaxf(cm, s[j]);
            float mnew = fmaxf(mrun, cm);
            float corr = __expf(mrun - mnew);
            lrun *= corr;
#pragma unroll
            for (int d = 0; d < HD; d++) o[d] *= corr;
#pragma unroll
            for (int j = 0; j < 8; j++) {
                int m = mb + j;
                if (m < NT) {
                    float p = __expf(s[j] - mnew);
                    lrun += p;
#pragma unroll
                    for (int dq = 0; dq < HD / 4; dq++) {
                        float4 v4 = *(const float4*)(vs + kvoff(m, dq));   // broadcast LDS128
                        o[4*dq+0] += p * v4.x;
                        o[4*dq+1] += p * v4.y;
                        o[4*dq+2] += p * v4.z;
                        o[4*dq+3] += p * v4.w;
                    }
                }
            }
            mrun = mnew;
        }

        float inv = 1.f / lrun;
        float* op = g_attn + ((size_t)b * NT + n) * CDIM + h * HD;
#pragma unroll
        for (int dq = 0; dq < HD / 4; dq++) {
            *(float4*)(op + 4 * dq) =
                make_float4(o[4*dq] * inv, o[4*dq+1] * inv, o[4*dq+2] * inv, o[4*dq+3] * inv);
        }
    }
}

// ============================ K2: output projection GEMM ============================
// out[i][:] = g_attn[i][:] @ proj_w.T + proj_b ; 64 rows per block
#define K2_ROWS 64
#define PW_PAD  100
#define SMEM_K2_FLOATS (CDIM*PW_PAD + K2_ROWS*CDIM)

__global__ __launch_bounds__(256)
void proj_kernel(const float* __restrict__ pw,
                 const float* __restrict__ pb,
                 float* __restrict__ out) {
    extern __shared__ float sm2[];
    float* pws = sm2;                          // [c][d], row stride 100
    float* as  = sm2 + CDIM * PW_PAD;          // [r][c]
    const int tid = threadIdx.x;
    const size_t row0 = (size_t)blockIdx.x * K2_ROWS;

    for (int i = tid; i < CDIM * CDIM; i += 256) {
        // i = d*96 + c : coalesced read, transposed store
        pws[(i % CDIM) * PW_PAD + (i / CDIM)] = __ldg(pw + i);
    }
    for (int i = tid; i < K2_ROWS * CDIM; i += 256) {
        as[i] = __ldg(g_attn + row0 * CDIM + i);
    }
    __syncthreads();

#pragma unroll
    for (int k = 0; k < 6; k++) {
        int idx = tid + k * 256;               // 0..1535 quads
        int r  = idx / 24;
        int d  = (idx % 24) * 4;
        float4 acc;
        acc.x = __ldg(pb + d + 0);
        acc.y = __ldg(pb + d + 1);
        acc.z = __ldg(pb + d + 2);
        acc.w = __ldg(pb + d + 3);
        const float* arow = as + r * CDIM;
#pragma unroll 4
        for (int c = 0; c < CDIM; c++) {
            float xv = arow[c];
            float4 w4 = *(const float4*)(pws + c * PW_PAD + d);
            acc.x += xv * w4.x;
            acc.y += xv * w4.y;
            acc.z += xv * w4.z;
            acc.w += xv * w4.w;
        }
        *(float4*)(out + (row0 + r) * CDIM + d) = acc;
    }
}

// ============================ launch ============================
extern "C" void kernel_launch(void* const* d_in, const int* in_sizes, int n_in,
                              void* d_out, int out_size) {
    const float* x      = (const float*)d_in[0];
    const float* mask   = (const float*)d_in[1];
    const float* qkv_w  = (const float*)d_in[2];
    const float* qkv_b  = (const float*)d_in[3];
    const float* proj_w = (const float*)d_in[4];
    const float* proj_b = (const float*)d_in[5];
    const float* rpb    = (const float*)d_in[6];
    const int*   ridx   = (const int*)d_in[7];
    float* out = (float*)d_out;

    cudaFuncSetAttribute(attn_kernel, cudaFuncAttributeMaxDynamicSharedMemorySize,
                         SMEM_K1_FLOATS * (int)sizeof(float));
    cudaFuncSetAttribute(proj_kernel, cudaFuncAttributeMaxDynamicSharedMemorySize,
                         SMEM_K2_FLOATS * (int)sizeof(float));

    bm_kernel<<<dim3(121, NW), 256>>>(mask, rpb, ridx);
    attn_kernel<<<dim3(BTOT, NH), 352, SMEM_K1_FLOATS * sizeof(float)>>>(x, qkv_w, qkv_b);
    proj_kernel<<<(BTOT * NT) / K2_ROWS, 256, SMEM_K2_FLOATS * sizeof(float)>>>(proj_w, proj_b, out);
}

// round 3
// speedup vs baseline: 1.0984x; 1.0984x over previous
#include <cuda_runtime.h>
#include <cstdio>

#define NT   343      // tokens per window (7*7*7)
#define CDIM 96       // embedding dim
#define HD   32       // head dim
#define NH   3        // heads
#define NW   64       // windows per batch group
#define BTOT 512      // total "b" (batch * windows)

typedef unsigned long long u64;

// ---------------- packed f32x2 helpers (sm_103a FFMA2 — ptxas won't emit these itself) ----------------
__device__ __forceinline__ u64 pack2(float lo, float hi) {
    u64 r; asm("mov.b64 %0, {%1, %2};" : "=l"(r) : "f"(lo), "f"(hi)); return r;
}
__device__ __forceinline__ void unpack2(u64 v, float& lo, float& hi) {
    asm("mov.b64 {%0, %1}, %2;" : "=f"(lo), "=f"(hi) : "l"(v));
}
__device__ __forceinline__ u64 ffma2(u64 a, u64 b, u64 c) {
    u64 d; asm("fma.rn.f32x2 %0, %1, %2, %3;" : "=l"(d) : "l"(a), "l"(b), "l"(c)); return d;
}
__device__ __forceinline__ u64 fmul2(u64 a, u64 b) {
    u64 d; asm("mul.rn.f32x2 %0, %1, %2;" : "=l"(d) : "l"(a), "l"(b)); return d;
}

// ---------------- scratch (static device globals: allocation-free) ----------------
__device__ float g_bm[(size_t)NW * NH * NT * NT];      // bias+mask, transposed [w,h][m][n]
__device__ float g_attn[(size_t)BTOT * NT * CDIM];     // attention output before proj

// swizzled K/V smem offset: row m, float4-quad dq  (conflict-free writes, broadcast reads)
__device__ __forceinline__ int kvoff(int m, int dq) {
    return m * HD + ((dq ^ (m & 7)) << 2);
}

// ============================ K0: bias+mask precombine (transposed) ============================
__global__ void bm_kernel(const float* __restrict__ mask,
                          const float* __restrict__ rpb,
                          const int*   __restrict__ ridx) {
    __shared__ float mt[32][33];
    __shared__ int   rt[32][33];
    const int w  = blockIdx.y;
    const int t  = blockIdx.x;            // 0..120
    const int tm = (t % 11) * 32;         // m tile base
    const int tn = (t / 11) * 32;         // n tile base
    const int tid = threadIdx.x;

    for (int i = tid; i < 1024; i += 256) {
        int r = i / 32, c = i % 32;
        int n = tn + r, m = tm + c;
        if (n < NT && m < NT) {
            mt[r][c] = mask[((size_t)w * NT + n) * NT + m];
            rt[r][c] = ridx[n * NT + m];
        }
    }
    __syncthreads();
    for (int i = tid; i < 1024; i += 256) {
        int r = i / 32, c = i % 32;
        int n = tn + c, m = tm + r;
        if (n < NT && m < NT) {
            float mv = mt[c][r];
            int   ri = rt[c][r];
#pragma unroll
            for (int hh = 0; hh < NH; hh++) {
                g_bm[(((size_t)w * NH + hh) * NT + m) * NT + n] = mv + __ldg(rpb + ri * NH + hh);
            }
        }
    }
}

// ============================ K1: fused QKV + attention per (b,h) ============================
#define SMEM_K1_FLOATS (CDIM*NT + NT*HD + NT*HD + CDIM*HD)

__global__ __launch_bounds__(352, 1)
void attn_kernel(const float* __restrict__ x,
                 const float* __restrict__ qkv_w,
                 const float* __restrict__ qkv_b) {
    extern __shared__ float sm[];
    float* xs = sm;                        // [c][n]  transposed x
    float* ks = xs + CDIM * NT;            // [m][d]  swizzled
    float* vs = ks + NT * HD;              // [m][d]  swizzled
    float* ws = vs + NT * HD;              // [c][d]  current weight matrix

    const int b   = blockIdx.x;
    const int h   = blockIdx.y;
    const int tid = threadIdx.x;
    const int n   = tid;                   // query/key row owned by this thread
    const float scale = 0.17677669529663689f;   // 32^-0.5

    // ---- load x[b] transposed into xs (coalesced float4 reads) ----
    {
        const float4* xb = (const float4*)(x + (size_t)b * NT * CDIM);
        for (int idx = tid; idx < NT * CDIM / 4; idx += blockDim.x) {
            float4 v = __ldg(xb + idx);
            int e = idx * 4;
            int row = e / CDIM, c = e % CDIM;
            xs[(c + 0) * NT + row] = v.x;
            xs[(c + 1) * NT + row] = v.y;
            xs[(c + 2) * NT + row] = v.z;
            xs[(c + 3) * NT + row] = v.w;
        }
    }
    __syncthreads();

    u64 q2[HD / 2];

    // ---- phase A: three weight passes (K, V, then Q last so q stays in regs) ----
#pragma unroll 1
    for (int pass = 0; pass < 3; pass++) {
        const int sel  = (pass == 0) ? 1 : (pass == 1) ? 2 : 0;   // k, v, q
        const int base = sel * CDIM + h * HD;

        // load W[sel,h] into ws[c][d]  (coalesced global reads)
        for (int i = tid; i < CDIM * HD; i += blockDim.x) {
            ws[(i % CDIM) * HD + (i / CDIM)] = __ldg(qkv_w + (size_t)base * CDIM + i);
        }
        __syncthreads();

        if (n < NT) {
            u64 acc2[HD / 2];
#pragma unroll
            for (int i = 0; i < HD / 2; i++)
                acc2[i] = pack2(__ldg(qkv_b + base + 2 * i), __ldg(qkv_b + base + 2 * i + 1));
#pragma unroll 4
            for (int c = 0; c < CDIM; c++) {
                float xv = xs[c * NT + n];
                u64 xv2 = pack2(xv, xv);
#pragma unroll
                for (int dq = 0; dq < HD / 4; dq++) {
                    ulonglong2 w2 = *(const ulonglong2*)(ws + c * HD + dq * 4);
                    acc2[2 * dq + 0] = ffma2(xv2, w2.x, acc2[2 * dq + 0]);
                    acc2[2 * dq + 1] = ffma2(xv2, w2.y, acc2[2 * dq + 1]);
                }
            }
            if (sel == 1) {
#pragma unroll
                for (int dq = 0; dq < HD / 4; dq++) {
                    ulonglong2 t; t.x = acc2[2 * dq]; t.y = acc2[2 * dq + 1];
                    *(ulonglong2*)(ks + kvoff(n, dq)) = t;
                }
            } else if (sel == 2) {
#pragma unroll
                for (int dq = 0; dq < HD / 4; dq++) {
                    ulonglong2 t; t.x = acc2[2 * dq]; t.y = acc2[2 * dq + 1];
                    *(ulonglong2*)(vs + kvoff(n, dq)) = t;
                }
            } else {
                u64 sc2 = pack2(scale, scale);
#pragma unroll
                for (int i = 0; i < HD / 2; i++) q2[i] = fmul2(acc2[i], sc2);
            }
        }
        __syncthreads();
    }

    // ---- phase B: online-softmax attention, 8-key chunks (packed f32x2) ----
    if (n < NT) {
        const float* bmrow = g_bm + (((size_t)(b % NW) * NH + h) * NT) * NT;  // [m][n]
        u64 o2[HD / 2];
#pragma unroll
        for (int i = 0; i < HD / 2; i++) o2[i] = 0ull;
        float mrun = -1e30f, lrun = 0.f;

        // 42 full chunks of 8 keys (no predication)
#pragma unroll 1
        for (int mb = 0; mb < 336; mb += 8) {
            float s[8];
#pragma unroll
            for (int j = 0; j < 8; j++)
                s[j] = __ldg(bmrow + (size_t)(mb + j) * NT + n);   // coalesced over n
#pragma unroll
            for (int j = 0; j < 8; j++) {
                int m = mb + j;
                u64 a0 = 0ull, a1 = 0ull;
#pragma unroll
                for (int dq = 0; dq < HD / 4; dq++) {
                    ulonglong2 k2 = *(const ulonglong2*)(ks + kvoff(m, dq));  // broadcast LDS128
                    a0 = ffma2(q2[2 * dq + 0], k2.x, a0);
                    a1 = ffma2(q2[2 * dq + 1], k2.y, a1);
                }
                float l0, h0, l1, h1;
                unpack2(a0, l0, h0); unpack2(a1, l1, h1);
                s[j] += (l0 + h0) + (l1 + h1);
            }
            float cm = fmaxf(fmaxf(fmaxf(s[0], s[1]), fmaxf(s[2], s[3])),
                             fmaxf(fmaxf(s[4], s[5]), fmaxf(s[6], s[7])));
            float mnew = fmaxf(mrun, cm);
            float corr = __expf(mrun - mnew);
            lrun *= corr;
            u64 corr2 = pack2(corr, corr);
#pragma unroll
            for (int i = 0; i < HD / 2; i++) o2[i] = fmul2(o2[i], corr2);
#pragma unroll
            for (int j = 0; j < 8; j++) {
                int m = mb + j;
                float p = __expf(s[j] - mnew);
                lrun += p;
                u64 p2 = pack2(p, p);
#pragma unroll
                for (int dq = 0; dq < HD / 4; dq++) {
                    ulonglong2 v2 = *(const ulonglong2*)(vs + kvoff(m, dq));  // broadcast LDS128
                    o2[2 * dq + 0] = ffma2(p2, v2.x, o2[2 * dq + 0]);
                    o2[2 * dq + 1] = ffma2(p2, v2.y, o2[2 * dq + 1]);
                }
            }
            mrun = mnew;
        }

        // tail: keys 336..342 (7 keys)
        {
            float s[7];
#pragma unroll
            for (int j = 0; j < 7; j++)
                s[j] = __ldg(bmrow + (size_t)(336 + j) * NT + n);
#pragma unroll
            for (int j = 0; j < 7; j++) {
                int m = 336 + j;
                u64 a0 = 0ull, a1 = 0ull;
#pragma unroll
                for (int dq = 0; dq < HD / 4; dq++) {
                    ulonglong2 k2 = *(const ulonglong2*)(ks + kvoff(m, dq));
                    a0 = ffma2(q2[2 * dq + 0], k2.x, a0);
                    a1 = ffma2(q2[2 * dq + 1], k2.y, a1);
                }
                float l0, h0, l1, h1;
                unpack2(a0, l0, h0); unpack2(a1, l1, h1);
                s[j] += (l0 + h0) + (l1 + h1);
            }
            float cm = s[0];
#pragma unroll
            for (int j = 1; j < 7; j++) cm = fmaxf(cm, s[j]);
            float mnew = fmaxf(mrun, cm);
            float corr = __expf(mrun - mnew);
            lrun *= corr;
            u64 corr2 = pack2(corr, corr);
#pragma unroll
            for (int i = 0; i < HD / 2; i++) o2[i] = fmul2(o2[i], corr2);
#pragma unroll
            for (int j = 0; j < 7; j++) {
                int m = 336 + j;
                float p = __expf(s[j] - mnew);
                lrun += p;
                u64 p2 = pack2(p, p);
#pragma unroll
                for (int dq = 0; dq < HD / 4; dq++) {
                    ulonglong2 v2 = *(const ulonglong2*)(vs + kvoff(m, dq));
                    o2[2 * dq + 0] = ffma2(p2, v2.x, o2[2 * dq + 0]);
                    o2[2 * dq + 1] = ffma2(p2, v2.y, o2[2 * dq + 1]);
                }
            }
        }

        float inv = 1.f / lrun;
        u64 inv2 = pack2(inv, inv);
        float* op = g_attn + ((size_t)b * NT + n) * CDIM + h * HD;
#pragma unroll
        for (int dq = 0; dq < HD / 4; dq++) {
            ulonglong2 t;
            t.x = fmul2(o2[2 * dq + 0], inv2);
            t.y = fmul2(o2[2 * dq + 1], inv2);
            *(ulonglong2*)(op + 4 * dq) = t;
        }
    }
}

// ============================ K2: output projection GEMM (packed) ============================
#define K2_ROWS 64
#define PW_PAD  100
#define SMEM_K2_FLOATS (CDIM*PW_PAD + K2_ROWS*CDIM)

__global__ __launch_bounds__(256)
void proj_kernel(const float* __restrict__ pw,
                 const float* __restrict__ pb,
                 float* __restrict__ out) {
    extern __shared__ float sm2[];
    float* pws = sm2;                          // [c][d], row stride 100
    float* as  = sm2 + CDIM * PW_PAD;          // [r][c]
    const int tid = threadIdx.x;
    const size_t row0 = (size_t)blockIdx.x * K2_ROWS;

    for (int i = tid; i < CDIM * CDIM; i += 256) {
        pws[(i % CDIM) * PW_PAD + (i / CDIM)] = __ldg(pw + i);
    }
    for (int i = tid; i < K2_ROWS * CDIM; i += 256) {
        as[i] = __ldg(g_attn + row0 * CDIM + i);
    }
    __syncthreads();

#pragma unroll
    for (int k = 0; k < 6; k++) {
        int idx = tid + k * 256;               // 0..1535 quads
        int r  = idx / 24;
        int d  = (idx % 24) * 4;
        u64 a0 = pack2(__ldg(pb + d + 0), __ldg(pb + d + 1));
        u64 a1 = pack2(__ldg(pb + d + 2), __ldg(pb + d + 3));
        const float* arow = as + r * CDIM;
#pragma unroll 4
        for (int c = 0; c < CDIM; c++) {
            float xv = arow[c];
            u64 xv2 = pack2(xv, xv);
            const u64* w2 = (const u64*)(pws + c * PW_PAD + d);
            a0 = ffma2(xv2, w2[0], a0);
            a1 = ffma2(xv2, w2[1], a1);
        }
        ulonglong2 t; t.x = a0; t.y = a1;
        *(ulonglong2*)(out + (row0 + r) * CDIM + d) = t;
    }
}

// ============================ launch ============================
extern "C" void kernel_launch(void* const* d_in, const int* in_sizes, int n_in,
                              void* d_out, int out_size) {
    const float* x      = (const float*)d_in[0];
    const float* mask   = (const float*)d_in[1];
    const float* qkv_w  = (const float*)d_in[2];
    const float* qkv_b  = (const float*)d_in[3];
    const float* proj_w = (const float*)d_in[4];
    const float* proj_b = (const float*)d_in[5];
    const float* rpb    = (const float*)d_in[6];
    const int*   ridx   = (const int*)d_in[7];
    float* out = (float*)d_out;

    cudaFuncSetAttribute(attn_kernel, cudaFuncAttributeMaxDynamicSharedMemorySize,
                         SMEM_K1_FLOATS * (int)sizeof(float));
    cudaFuncSetAttribute(proj_kernel, cudaFuncAttributeMaxDynamicSharedMemorySize,
                         SMEM_K2_FLOATS * (int)sizeof(float));

    bm_kernel<<<dim3(121, NW), 256>>>(mask, rpb, ridx);
    attn_kernel<<<dim3(BTOT, NH), 352, SMEM_K1_FLOATS * sizeof(float)>>>(x, qkv_w, qkv_b);
    proj_kernel<<<(BTOT * NT) / K2_ROWS, 256, SMEM_K2_FLOATS * sizeof(float)>>>(proj_w, proj_b, out);
}